// round 2
// baseline (speedup 1.0000x reference)
#include <cuda_runtime.h>
#include <math.h>

// Problem constants (fixed by the dataset)
#define BB    16
#define CCH   128      // Cin = Cout = 128
#define NN    8192
#define MODES 64
#define ROWS  (BB*CCH) // 2048
#define KSPLIT 32
#define KCHUNK (NN/KSPLIT) // 256

// Scratch (static device globals — allowed; no cudaMalloc)
__device__ float g_T[128 * NN];                    // 4MB  [j][n]: j<64 cos(2pi j n/N), j>=64 sin(2pi (j-64) n/N)
__device__ float g_Ppart[(size_t)KSPLIT * ROWS * 128]; // 32MB split-K partials [ks][r][j]
__device__ float g_PsumT[128 * ROWS];              // 1MB  [j][r]
__device__ float g_wT[MODES * CCH * CCH * 2];      // 8MB  [m][o][i][re,im]
__device__ float g_C[BB * CCH * 128];              // 1MB  coefficients [b][o][j]

// ---------------------------------------------------------------------------
// Basis table: g_T[j][n]
// ---------------------------------------------------------------------------
__global__ void fill_T() {
    int idx = blockIdx.x * blockDim.x + threadIdx.x;   // 0 .. 128*8192-1
    int j = idx >> 13;
    int n = idx & (NN - 1);
    int m = j & 63;
    int t = (m * n) & (NN - 1);
    float frac = (float)t * (1.0f / 4096.0f);          // theta = pi*frac = 2pi m n / N
    float s, c;
    sincospif(frac, &s, &c);
    g_T[idx] = (j < MODES) ? c : s;
}

// ---------------------------------------------------------------------------
// w_spec [i][o][m][2] -> g_wT [m][o][i][2]   (coalesced both sides via 4-i packs)
// ---------------------------------------------------------------------------
__global__ void transpose_w(const float* __restrict__ w_spec) {
    int idx = blockIdx.x * blockDim.x + threadIdx.x;   // 0 .. 64*128*32-1
    int m  = idx & 63;
    int o  = (idx >> 6) & 127;
    int ib = idx >> 13;                                 // 0..31
    float2 v[4];
#pragma unroll
    for (int q = 0; q < 4; q++) {
        int i = ib * 4 + q;
        v[q] = *(const float2*)(w_spec + ((size_t)(i * CCH + o) * MODES + m) * 2);
    }
    float* dst = g_wT + ((size_t)(m * CCH + o) * CCH + ib * 4) * 2;
    *(float4*)(dst)     = make_float4(v[0].x, v[0].y, v[1].x, v[1].y);
    *(float4*)(dst + 4) = make_float4(v[2].x, v[2].y, v[3].x, v[3].y);
}

// ---------------------------------------------------------------------------
// Forward GEMM (split-K): Ppart[ks][r][j] = sum_{k in chunk} x[r][k] * T[j][k]
// r = b*128+i (2048 rows), j = 0..127. Tiles: 128x128, K-tile 32, 8x8/thread.
// ---------------------------------------------------------------------------
__global__ __launch_bounds__(256) void gemm_fwd(const float* __restrict__ x) {
    int ks = blockIdx.x;       // 0..31
    int mt = blockIdx.y;       // 0..15
    __shared__ float As[32][128];
    __shared__ float Bs[32][128];
    int t  = threadIdx.x;
    int tx = t & 15, ty = t >> 4;
    float acc[8][8];
#pragma unroll
    for (int u = 0; u < 8; u++)
#pragma unroll
        for (int v = 0; v < 8; v++) acc[u][v] = 0.f;

    const float* Ag = x + (size_t)(mt * 128) * NN;
    int kbase0 = ks * KCHUNK;

    for (int kb = 0; kb < KCHUNK; kb += 32) {
        int kbase = kbase0 + kb;
#pragma unroll
        for (int q = 0; q < 4; q++) {        // A: 128 rows x 32 k, transposed store
            int idx = t + q * 256;
            int row = idx >> 3;
            int k4  = idx & 7;
            float4 v = *(const float4*)(Ag + (size_t)row * NN + kbase + k4 * 4);
            As[k4 * 4 + 0][row] = v.x; As[k4 * 4 + 1][row] = v.y;
            As[k4 * 4 + 2][row] = v.z; As[k4 * 4 + 3][row] = v.w;
        }
#pragma unroll
        for (int q = 0; q < 4; q++) {        // B: 128 basis rows x 32 k
            int idx = t + q * 256;
            int row = idx >> 3;
            int k4  = idx & 7;
            float4 v = *(const float4*)(g_T + (size_t)row * NN + kbase + k4 * 4);
            Bs[k4 * 4 + 0][row] = v.x; Bs[k4 * 4 + 1][row] = v.y;
            Bs[k4 * 4 + 2][row] = v.z; Bs[k4 * 4 + 3][row] = v.w;
        }
        __syncthreads();
#pragma unroll
        for (int kk = 0; kk < 32; kk++) {
            float4 a0 = *(const float4*)&As[kk][ty * 8];
            float4 a1 = *(const float4*)&As[kk][ty * 8 + 4];
            float4 b0 = *(const float4*)&Bs[kk][tx * 8];
            float4 b1 = *(const float4*)&Bs[kk][tx * 8 + 4];
            float a[8] = {a0.x, a0.y, a0.z, a0.w, a1.x, a1.y, a1.z, a1.w};
            float b[8] = {b0.x, b0.y, b0.z, b0.w, b1.x, b1.y, b1.z, b1.w};
#pragma unroll
            for (int u = 0; u < 8; u++)
#pragma unroll
                for (int v = 0; v < 8; v++) acc[u][v] = fmaf(a[u], b[v], acc[u][v]);
        }
        __syncthreads();
    }

    float* op = g_Ppart + ((size_t)ks * ROWS + mt * 128) * 128;
#pragma unroll
    for (int u = 0; u < 8; u++) {
        int r = ty * 8 + u;
        *(float4*)(op + (size_t)r * 128 + tx * 8)     = make_float4(acc[u][0], acc[u][1], acc[u][2], acc[u][3]);
        *(float4*)(op + (size_t)r * 128 + tx * 8 + 4) = make_float4(acc[u][4], acc[u][5], acc[u][6], acc[u][7]);
    }
}

// ---------------------------------------------------------------------------
// Reduce split-K partials and transpose: g_PsumT[j][r] = sum_ks Ppart[ks][r][j]
// ---------------------------------------------------------------------------
__global__ __launch_bounds__(256) void reduce_transpose() {
    int rt = blockIdx.x;  // 0..15 -> r tile of 128
    int jt = blockIdx.y;  // 0..3  -> j tile of 32
    int r0 = rt * 128, j0 = jt * 32;
    int t = threadIdx.x;
    int jj = t & 31, rr = t >> 5;   // rr 0..7
    float acc[16];
#pragma unroll
    for (int e = 0; e < 16; e++) acc[e] = 0.f;
    for (int k = 0; k < KSPLIT; k++) {
        const float* p = g_Ppart + ((size_t)k * ROWS + r0) * 128 + j0 + jj;
#pragma unroll
        for (int e = 0; e < 16; e++)
            acc[e] += p[(size_t)(rr + e * 8) * 128];
    }
    __shared__ float tile[32][129];
#pragma unroll
    for (int e = 0; e < 16; e++) tile[jj][rr + e * 8] = acc[e];
    __syncthreads();
#pragma unroll
    for (int w = 0; w < 16; w++) {
        int flat = t + w * 256;       // 0..4095
        int jl = flat >> 7;           // 0..31
        int rl = flat & 127;
        g_PsumT[(size_t)(j0 + jl) * ROWS + r0 + rl] = tile[jl][rl];
    }
}

// ---------------------------------------------------------------------------
// Mode mix: complex channel contraction + irfft coefficient scaling.
//   Fre[b,i,m] =  PsumT[m][r],  Fim[b,i,m] = -PsumT[64+m][r]
//   out_m = sum_i F * w  (complex)
//   C[b][o][m]    = (m==0?1:2)/N * Re(out_m)
//   C[b][o][64+m] = (m==0?0:-2)/N * Im(out_m)   (sin-basis coefficient)
// ---------------------------------------------------------------------------
__global__ __launch_bounds__(128) void mode_mix() {
    int m  = blockIdx.x;   // 0..63
    int bg = blockIdx.y;   // 0..3  (4 batches each)
    int o  = threadIdx.x;  // 0..127
    __shared__ float Fre[4][128], Fim[4][128];
#pragma unroll
    for (int q = 0; q < 4; q++) {
        int r = (bg * 4 + q) * 128 + o;     // i = o for the load role
        Fre[q][o] =  g_PsumT[(size_t)m * ROWS + r];
        Fim[q][o] = -g_PsumT[(size_t)(64 + m) * ROWS + r];
    }
    __syncthreads();
    float accR[4] = {0, 0, 0, 0}, accI[4] = {0, 0, 0, 0};
    const float2* wrow = (const float2*)g_wT + (size_t)(m * CCH + o) * CCH;
    for (int i = 0; i < CCH; i++) {
        float2 w = wrow[i];
#pragma unroll
        for (int q = 0; q < 4; q++) {
            float fr = Fre[q][i], fi = Fim[q][i];
            accR[q] = fmaf(fr, w.x, fmaf(-fi, w.y, accR[q]));
            accI[q] = fmaf(fr, w.y, fmaf( fi, w.x, accI[q]));
        }
    }
    float sR = (m == 0) ? (1.0f / (float)NN) : (2.0f / (float)NN);
    float sI = (m == 0) ? 0.0f : (-2.0f / (float)NN);
#pragma unroll
    for (int q = 0; q < 4; q++) {
        int b = bg * 4 + q;
        g_C[((size_t)b * CCH + o) * 128 + m]      = accR[q] * sR;
        g_C[((size_t)b * CCH + o) * 128 + 64 + m] = accI[q] * sI;
    }
}

// ---------------------------------------------------------------------------
// Fused inverse DFT + 1x1 conv + bias + exact GELU.
// Per b: Out[o][n] = gelu( sum_{j<128} C[b][o][j]*T[j][n]
//                        + sum_{i<128} w_conv[o][i]*x[b][i][n] + b_conv[o] )
// Single GEMM with K=256 (A = [C | w_conv], B = [T ; x_b]).
// ---------------------------------------------------------------------------
__global__ __launch_bounds__(256) void gemm_inv(const float* __restrict__ x,
                                                const float* __restrict__ w_conv,
                                                const float* __restrict__ b_conv,
                                                float* __restrict__ out) {
    int nt = blockIdx.x;   // 0..63
    int b  = blockIdx.y;   // 0..15
    __shared__ float As[32][128];
    __shared__ float Bs[32][128];
    int t  = threadIdx.x;
    int tx = t & 15, ty = t >> 4;
    float acc[8][8];
#pragma unroll
    for (int u = 0; u < 8; u++)
#pragma unroll
        for (int v = 0; v < 8; v++) acc[u][v] = 0.f;

    const float* Cb = g_C + (size_t)b * CCH * 128;
    const float* Xb = x + (size_t)b * CCH * NN;
    int n0 = nt * 128;

    for (int kt = 0; kt < 256; kt += 32) {
        const float* Asrc = (kt < 128) ? (Cb + kt) : (w_conv + (kt - 128));
#pragma unroll
        for (int q = 0; q < 4; q++) {        // A: 128 rows(o) x 32 k, transposed store
            int idx = t + q * 256;
            int row = idx >> 3;
            int k4  = idx & 7;
            float4 v = *(const float4*)(Asrc + (size_t)row * 128 + k4 * 4);
            As[k4 * 4 + 0][row] = v.x; As[k4 * 4 + 1][row] = v.y;
            As[k4 * 4 + 2][row] = v.z; As[k4 * 4 + 3][row] = v.w;
        }
#pragma unroll
        for (int q = 0; q < 4; q++) {        // B: 32 k-rows x 128 n, direct
            int idx = t + q * 256;
            int row = idx >> 5;              // 0..31 (uniform per warp)
            int c4  = idx & 31;
            int k   = kt + row;
            const float* Bsrc = (k < 128) ? (g_T + (size_t)k * NN + n0)
                                          : (Xb + (size_t)(k - 128) * NN + n0);
            *(float4*)&Bs[row][c4 * 4] = *(const float4*)(Bsrc + c4 * 4);
        }
        __syncthreads();
#pragma unroll
        for (int kk = 0; kk < 32; kk++) {
            float4 a0 = *(const float4*)&As[kk][ty * 8];
            float4 a1 = *(const float4*)&As[kk][ty * 8 + 4];
            float4 b0 = *(const float4*)&Bs[kk][tx * 8];
            float4 b1 = *(const float4*)&Bs[kk][tx * 8 + 4];
            float a[8] = {a0.x, a0.y, a0.z, a0.w, a1.x, a1.y, a1.z, a1.w};
            float bb[8] = {b0.x, b0.y, b0.z, b0.w, b1.x, b1.y, b1.z, b1.w};
#pragma unroll
            for (int u = 0; u < 8; u++)
#pragma unroll
                for (int v = 0; v < 8; v++) acc[u][v] = fmaf(a[u], bb[v], acc[u][v]);
        }
        __syncthreads();
    }

#pragma unroll
    for (int u = 0; u < 8; u++) {
        int o = ty * 8 + u;
        float bias = b_conv[o];
        float r[8];
#pragma unroll
        for (int v = 0; v < 8; v++) {
            float val = acc[u][v] + bias;
            r[v] = 0.5f * val * (1.0f + erff(val * 0.70710678118654752f));
        }
        float* op = out + ((size_t)(b * CCH + o)) * NN + n0 + tx * 8;
        *(float4*)(op)     = make_float4(r[0], r[1], r[2], r[3]);
        *(float4*)(op + 4) = make_float4(r[4], r[5], r[6], r[7]);
    }
}

// ---------------------------------------------------------------------------
extern "C" void kernel_launch(void* const* d_in, const int* in_sizes, int n_in,
                              void* d_out, int out_size) {
    const float* x      = (const float*)d_in[0];
    const float* w_spec = (const float*)d_in[1];
    const float* w_conv = (const float*)d_in[2];
    const float* b_conv = (const float*)d_in[3];
    float* out = (float*)d_out;

    fill_T<<<(128 * NN) / 256, 256>>>();
    transpose_w<<<(MODES * CCH * 32) / 256, 256>>>(w_spec);
    gemm_fwd<<<dim3(KSPLIT, ROWS / 128), 256>>>(x);
    reduce_transpose<<<dim3(ROWS / 128, 4), 256>>>();
    mode_mix<<<dim3(MODES, 4), 128>>>();
    gemm_inv<<<dim3(NN / 128, BB), 256>>>(x, w_conv, b_conv, out);
}

// round 4
// speedup vs baseline: 1.5087x; 1.5087x over previous
#include <cuda_runtime.h>
#include <cuda_bf16.h>
#include <math.h>
#include <stdint.h>

#define NN    8192
#define BB    16
#define CCH   128
#define MODES 64
#define KSPLIT 16

// ---------------- scratch (static device globals) ----------------
__device__ __nv_bfloat16 g_Tfh[128 * NN];                 // fwd basis hi [j][n]
__device__ __nv_bfloat16 g_Tfl[128 * NN];                 // fwd basis lo
__device__ __nv_bfloat16 g_Tth[NN * 128];                 // inv basis hi [n][j]
__device__ __nv_bfloat16 g_Ttl[NN * 128];                 // inv basis lo
__device__ __nv_bfloat16 g_xth[(size_t)BB * NN * 128];    // x^T hi [b][n][i]
__device__ __nv_bfloat16 g_xtl[(size_t)BB * NN * 128];    // x^T lo
__device__ __nv_bfloat16 g_Abh[BB * 128 * 256];           // inv A hi [b][o][k]
__device__ __nv_bfloat16 g_Abl[BB * 128 * 256];           // inv A lo
__device__ float         g_P  [(size_t)KSPLIT * 2048 * 128]; // fwd partials [ks][r][j]
__device__ float         g_wT [MODES * CCH * CCH * 2];    // [m][o][i][re,im]

// ---------------- helpers ----------------
__device__ __forceinline__ uint32_t smem_u32(const void* p) {
    uint32_t a;
    asm("{ .reg .u64 t; cvta.to.shared.u64 t, %1; cvt.u32.u64 %0, t; }" : "=r"(a) : "l"(p));
    return a;
}
#define LDSM4(R, addr) \
    asm volatile("ldmatrix.sync.aligned.m8n8.x4.shared.b16 {%0,%1,%2,%3}, [%4];" \
        : "=r"((R)[0]), "=r"((R)[1]), "=r"((R)[2]), "=r"((R)[3]) : "r"(addr))

__device__ __forceinline__ void mma16816(float* c, const uint32_t* a, uint32_t b0, uint32_t b1) {
    asm volatile("mma.sync.aligned.m16n8k16.row.col.f32.bf16.bf16.f32 "
        "{%0,%1,%2,%3}, {%4,%5,%6,%7}, {%8,%9}, {%0,%1,%2,%3};"
        : "+f"(c[0]), "+f"(c[1]), "+f"(c[2]), "+f"(c[3])
        : "r"(a[0]), "r"(a[1]), "r"(a[2]), "r"(a[3]), "r"(b0), "r"(b1));
}
__device__ __forceinline__ uint32_t pack2(__nv_bfloat16 a, __nv_bfloat16 b) {
    return (uint32_t)__bfloat16_as_ushort(a) | ((uint32_t)__bfloat16_as_ushort(b) << 16);
}
__device__ __forceinline__ void split4(float4 v, uint2& hi, uint2& lo) {
    __nv_bfloat16 h0 = __float2bfloat16(v.x), h1 = __float2bfloat16(v.y);
    __nv_bfloat16 h2 = __float2bfloat16(v.z), h3 = __float2bfloat16(v.w);
    __nv_bfloat16 l0 = __float2bfloat16(v.x - __bfloat162float(h0));
    __nv_bfloat16 l1 = __float2bfloat16(v.y - __bfloat162float(h1));
    __nv_bfloat16 l2 = __float2bfloat16(v.z - __bfloat162float(h2));
    __nv_bfloat16 l3 = __float2bfloat16(v.w - __bfloat162float(h3));
    hi = make_uint2(pack2(h0, h1), pack2(h2, h3));
    lo = make_uint2(pack2(l0, l1), pack2(l2, l3));
}

// SMEM stage layout: per stage, A-hi / A-lo / B-hi / B-lo, each 128 rows x 80B
#define ST_STRIDE 80
#define ST_AH 0
#define ST_AL 10240
#define ST_BH 20480
#define ST_BL 30720
#define ST_SZ 40960
#define SMEM_BYTES (2 * ST_SZ)

// ---------------------------------------------------------------------------
// Prep kernels
// ---------------------------------------------------------------------------
__global__ void fill_Tf() {
    int idx = blockIdx.x * blockDim.x + threadIdx.x;   // 128*8192, [j][n]
    int j = idx >> 13;
    int n = idx & (NN - 1);
    int m = j & 63;
    int t = (m * n) & (NN - 1);
    float s, c;
    sincospif((float)t * (1.0f / 4096.0f), &s, &c);
    float v = (j < MODES) ? c : s;
    __nv_bfloat16 h = __float2bfloat16(v);
    g_Tfh[idx] = h;
    g_Tfl[idx] = __float2bfloat16(v - __bfloat162float(h));
}

__global__ void fill_Tt() {
    int idx = blockIdx.x * blockDim.x + threadIdx.x;   // 8192*128, [n][j]
    int n = idx >> 7;
    int j = idx & 127;
    int m = j & 63;
    int t = (m * n) & (NN - 1);
    float s, c;
    sincospif((float)t * (1.0f / 4096.0f), &s, &c);
    float v = (j < MODES) ? c : s;
    __nv_bfloat16 h = __float2bfloat16(v);
    g_Tth[idx] = h;
    g_Ttl[idx] = __float2bfloat16(v - __bfloat162float(h));
}

__global__ void transpose_w(const float* __restrict__ w_spec) {
    int idx = blockIdx.x * blockDim.x + threadIdx.x;   // 64*128*32
    int m  = idx & 63;
    int o  = (idx >> 6) & 127;
    int ib = idx >> 13;
    float2 v[4];
#pragma unroll
    for (int q = 0; q < 4; q++) {
        int i = ib * 4 + q;
        v[q] = *(const float2*)(w_spec + ((size_t)(i * CCH + o) * MODES + m) * 2);
    }
    float* dst = g_wT + ((size_t)(m * CCH + o) * CCH + ib * 4) * 2;
    *(float4*)(dst)     = make_float4(v[0].x, v[0].y, v[1].x, v[1].y);
    *(float4*)(dst + 4) = make_float4(v[2].x, v[2].y, v[3].x, v[3].y);
}

__global__ void prep_xt(const float* __restrict__ x) {
    __shared__ float tile[32][33];
    int n0 = blockIdx.x * 32, i0 = blockIdx.y * 32, b = blockIdx.z;
    int tx = threadIdx.x, ty = threadIdx.y;
    const float* xb = x + ((size_t)b * 128 + i0) * NN + n0;
#pragma unroll
    for (int e = 0; e < 4; e++)
        tile[ty + e * 8][tx] = xb[(size_t)(ty + e * 8) * NN + tx];
    __syncthreads();
#pragma unroll
    for (int e = 0; e < 4; e++) {
        int n = ty + e * 8;
        float v = tile[tx][n];
        __nv_bfloat16 h = __float2bfloat16(v);
        size_t o = ((size_t)b * NN + n0 + n) * 128 + i0 + tx;
        g_xth[o] = h;
        g_xtl[o] = __float2bfloat16(v - __bfloat162float(h));
    }
}

__global__ void prep_wconv(const float* __restrict__ w_conv) {
    int idx = blockIdx.x * blockDim.x + threadIdx.x;   // 16*128*128
    int b = idx >> 14;
    int o = (idx >> 7) & 127;
    int i = idx & 127;
    float v = w_conv[o * 128 + i];
    __nv_bfloat16 h = __float2bfloat16(v);
    size_t d = ((size_t)b * 128 + o) * 256 + 128 + i;
    g_Abh[d] = h;
    g_Abl[d] = __float2bfloat16(v - __bfloat162float(h));
}

// ---------------------------------------------------------------------------
// Shared compute: one 128x128x32 k-tile with hi/lo split (3 passes)
// ---------------------------------------------------------------------------
__device__ __forceinline__ void compute_tile(float acc[2][8][4], uint32_t stg,
                                             int wm, int wn, int lane) {
#pragma unroll
    for (int s16 = 0; s16 < 2; s16++) {
        uint32_t ah[2][4], al[2][4];
        uint32_t aaddr = stg + ST_AH + (uint32_t)(wm * 32 + (lane & 15)) * ST_STRIDE
                       + s16 * 32 + (lane >> 4) * 16;
        LDSM4(ah[0], aaddr);
        LDSM4(ah[1], aaddr + 16 * ST_STRIDE);
        LDSM4(al[0], aaddr + (ST_AL - ST_AH));
        LDSM4(al[1], aaddr + (ST_AL - ST_AH) + 16 * ST_STRIDE);
        uint32_t n_off = (lane & 7) + ((lane >> 4) << 3);
        uint32_t kb = ((lane >> 3) & 1) * 16;
        uint32_t baddr = stg + ST_BH + (uint32_t)(wn * 64 + n_off) * ST_STRIDE
                       + s16 * 32 + kb;
#pragma unroll
        for (int nb = 0; nb < 4; nb++) {
            uint32_t bh[4], bl[4];
            LDSM4(bh, baddr + nb * 16 * ST_STRIDE);
            LDSM4(bl, baddr + nb * 16 * ST_STRIDE + (ST_BL - ST_BH));
#pragma unroll
            for (int half = 0; half < 2; half++) {
                int n = nb * 2 + half;
#pragma unroll
                for (int m = 0; m < 2; m++) {
                    mma16816(acc[m][n], ah[m], bh[half * 2], bh[half * 2 + 1]);
                    mma16816(acc[m][n], ah[m], bl[half * 2], bl[half * 2 + 1]);
                    mma16816(acc[m][n], al[m], bh[half * 2], bh[half * 2 + 1]);
                }
            }
        }
    }
}

// ---------------------------------------------------------------------------
// Forward GEMM: P[ks][r][j] = sum_{k in chunk} x[r][k] * T[j][k]
// grid (KSPLIT, 16), 256 threads. K-chunk 512 = 16 tiles of 32.
// ---------------------------------------------------------------------------
__global__ __launch_bounds__(256, 1) void gemm_fwd_mma(const float* __restrict__ x) {
    extern __shared__ char smem[];
    uint32_t sb = smem_u32(smem);
    int t = threadIdx.x, lane = t & 31, wid = t >> 5;
    int wm = wid & 3, wn = wid >> 2;
    int ks = blockIdx.x, mt = blockIdx.y;
    int r0 = mt * 128, kbase = ks * (NN / KSPLIT);
    const int NT = (NN / KSPLIT) / 32;   // 16

    float acc[2][8][4];
#pragma unroll
    for (int m = 0; m < 2; m++)
#pragma unroll
        for (int n = 0; n < 8; n++)
#pragma unroll
            for (int e = 0; e < 4; e++) acc[m][n][e] = 0.f;

    // precomputed per-thread load indices
    int arow = t >> 3, ak4 = t & 7;          // A: 4 chunks of (row+=32)
    int brow = t >> 2, bu = t & 3;           // B: 2 chunks of (row+=64)

    // prologue: fill stage 0
    {
        char* st = smem;
        int k0 = kbase;
#pragma unroll
        for (int q = 0; q < 4; q++) {
            int row = arow + q * 32;
            float4 v = *(const float4*)(x + (size_t)(r0 + row) * NN + k0 + ak4 * 4);
            uint2 hi, lo; split4(v, hi, lo);
            *(uint2*)(st + ST_AH + row * ST_STRIDE + ak4 * 8) = hi;
            *(uint2*)(st + ST_AL + row * ST_STRIDE + ak4 * 8) = lo;
        }
#pragma unroll
        for (int q = 0; q < 2; q++) {
            int row = brow + q * 64;
            *(uint4*)(st + ST_BH + row * ST_STRIDE + bu * 16) =
                *(const uint4*)(g_Tfh + (size_t)row * NN + k0 + bu * 8);
            *(uint4*)(st + ST_BL + row * ST_STRIDE + bu * 16) =
                *(const uint4*)(g_Tfl + (size_t)row * NN + k0 + bu * 8);
        }
    }
    __syncthreads();

    for (int tile = 0; tile < NT; tile++) {
        int cur = tile & 1;
        float4 va[4]; uint4 vb[4];
        bool has_next = (tile + 1 < NT);
        if (has_next) {
            int k0 = kbase + (tile + 1) * 32;
#pragma unroll
            for (int q = 0; q < 4; q++)
                va[q] = *(const float4*)(x + (size_t)(r0 + arow + q * 32) * NN + k0 + ak4 * 4);
#pragma unroll
            for (int q = 0; q < 2; q++) {
                vb[q]     = *(const uint4*)(g_Tfh + (size_t)(brow + q * 64) * NN + k0 + bu * 8);
                vb[q + 2] = *(const uint4*)(g_Tfl + (size_t)(brow + q * 64) * NN + k0 + bu * 8);
            }
        }
        compute_tile(acc, sb + cur * ST_SZ, wm, wn, lane);
        if (has_next) {
            char* st = smem + (cur ^ 1) * ST_SZ;
#pragma unroll
            for (int q = 0; q < 4; q++) {
                int row = arow + q * 32;
                uint2 hi, lo; split4(va[q], hi, lo);
                *(uint2*)(st + ST_AH + row * ST_STRIDE + ak4 * 8) = hi;
                *(uint2*)(st + ST_AL + row * ST_STRIDE + ak4 * 8) = lo;
            }
#pragma unroll
            for (int q = 0; q < 2; q++) {
                *(uint4*)(st + ST_BH + (brow + q * 64) * ST_STRIDE + bu * 16) = vb[q];
                *(uint4*)(st + ST_BL + (brow + q * 64) * ST_STRIDE + bu * 16) = vb[q + 2];
            }
        }
        __syncthreads();
    }

    // epilogue: write partials
    float* P = g_P + ((size_t)ks * 2048 + r0) * 128;
#pragma unroll
    for (int m = 0; m < 2; m++) {
        int r = wm * 32 + m * 16 + (lane >> 2);
#pragma unroll
        for (int n = 0; n < 8; n++) {
            int j = wn * 64 + n * 8 + (lane & 3) * 2;
            *(float2*)(P + (size_t)r * 128 + j)       = make_float2(acc[m][n][0], acc[m][n][1]);
            *(float2*)(P + (size_t)(r + 8) * 128 + j) = make_float2(acc[m][n][2], acc[m][n][3]);
        }
    }
}

// ---------------------------------------------------------------------------
// Mode mix (folds split-K reduce) -> bf16 hi/lo coefficients in g_Ab
// ---------------------------------------------------------------------------
__global__ __launch_bounds__(128) void mode_mix() {
    int m = blockIdx.x, b = blockIdx.y, o = threadIdx.x;
    __shared__ float Fre[128], Fim[128];
    float sr = 0.f, si = 0.f;
#pragma unroll
    for (int ks = 0; ks < KSPLIT; ks++) {
        const float* p = g_P + ((size_t)ks * 2048 + b * 128 + o) * 128;
        sr += p[m];
        si += p[64 + m];
    }
    Fre[o] = sr;
    Fim[o] = -si;
    __syncthreads();
    float aR = 0.f, aI = 0.f;
    const float2* wrow = (const float2*)g_wT + (size_t)(m * CCH + o) * CCH;
    for (int i = 0; i < CCH; i++) {
        float2 w = wrow[i];
        float fr = Fre[i], fi = Fim[i];
        aR = fmaf(fr, w.x, fmaf(-fi, w.y, aR));
        aI = fmaf(fr, w.y, fmaf( fi, w.x, aI));
    }
    float sR = (m == 0) ? (1.0f / (float)NN) : (2.0f / (float)NN);
    float sI = (m == 0) ? 0.0f : (-2.0f / (float)NN);
    float cR = aR * sR, cI = aI * sI;
    size_t base = ((size_t)b * 128 + o) * 256;
    __nv_bfloat16 hR = __float2bfloat16(cR);
    __nv_bfloat16 hI = __float2bfloat16(cI);
    g_Abh[base + m]      = hR;
    g_Abl[base + m]      = __float2bfloat16(cR - __bfloat162float(hR));
    g_Abh[base + 64 + m] = hI;
    g_Abl[base + 64 + m] = __float2bfloat16(cI - __bfloat162float(hI));
}

// ---------------------------------------------------------------------------
// Inverse GEMM (fused iDFT + conv1x1 + bias + exact GELU)
// D[o][n] = sum_k A[o][k]*B[n][k], K=256. grid (64 n-tiles, 16 batches).
// ---------------------------------------------------------------------------
__global__ __launch_bounds__(256, 1) void gemm_inv_mma(const float* __restrict__ b_conv,
                                                       float* __restrict__ out) {
    extern __shared__ char smem[];
    uint32_t sb = smem_u32(smem);
    int t = threadIdx.x, lane = t & 31, wid = t >> 5;
    int wm = wid & 3, wn = wid >> 2;
    int nt = blockIdx.x, b = blockIdx.y;
    int n0 = nt * 128;
    const int NT = 8;   // 256 / 32

    const __nv_bfloat16* Abh = g_Abh + (size_t)b * 32768;
    const __nv_bfloat16* Abl = g_Abl + (size_t)b * 32768;
    const __nv_bfloat16* Xh = g_xth + ((size_t)b * NN + n0) * 128;
    const __nv_bfloat16* Xl = g_xtl + ((size_t)b * NN + n0) * 128;
    const __nv_bfloat16* Th = g_Tth + (size_t)n0 * 128;
    const __nv_bfloat16* Tl = g_Ttl + (size_t)n0 * 128;

    float acc[2][8][4];
#pragma unroll
    for (int m = 0; m < 2; m++)
#pragma unroll
        for (int n = 0; n < 8; n++)
#pragma unroll
            for (int e = 0; e < 4; e++) acc[m][n][e] = 0.f;

    int row = t >> 2, u = t & 3;    // both A and B: 2 chunks of (row+=64)

    // prologue
    {
        char* st = smem;
#pragma unroll
        for (int q = 0; q < 2; q++) {
            int r = row + q * 64;
            *(uint4*)(st + ST_AH + r * ST_STRIDE + u * 16) = *(const uint4*)(Abh + (size_t)r * 256 + u * 8);
            *(uint4*)(st + ST_AL + r * ST_STRIDE + u * 16) = *(const uint4*)(Abl + (size_t)r * 256 + u * 8);
            *(uint4*)(st + ST_BH + r * ST_STRIDE + u * 16) = *(const uint4*)(Th + (size_t)r * 128 + u * 8);
            *(uint4*)(st + ST_BL + r * ST_STRIDE + u * 16) = *(const uint4*)(Tl + (size_t)r * 128 + u * 8);
        }
    }
    __syncthreads();

    for (int tile = 0; tile < NT; tile++) {
        int cur = tile & 1;
        uint4 vreg[8];
        bool has_next = (tile + 1 < NT);
        if (has_next) {
            int k0 = (tile + 1) * 32;
            const __nv_bfloat16* Bh = (k0 < 128) ? (Th + k0) : (Xh + (k0 - 128));
            const __nv_bfloat16* Bl = (k0 < 128) ? (Tl + k0) : (Xl + (k0 - 128));
#pragma unroll
            for (int q = 0; q < 2; q++) {
                int r = row + q * 64;
                vreg[q]     = *(const uint4*)(Abh + (size_t)r * 256 + k0 + u * 8);
                vreg[q + 2] = *(const uint4*)(Abl + (size_t)r * 256 + k0 + u * 8);
                vreg[q + 4] = *(const uint4*)(Bh + (size_t)r * 128 + u * 8);
                vreg[q + 6] = *(const uint4*)(Bl + (size_t)r * 128 + u * 8);
            }
        }
        compute_tile(acc, sb + cur * ST_SZ, wm, wn, lane);
        if (has_next) {
            char* st = smem + (cur ^ 1) * ST_SZ;
#pragma unroll
            for (int q = 0; q < 2; q++) {
                int r = row + q * 64;
                *(uint4*)(st + ST_AH + r * ST_STRIDE + u * 16) = vreg[q];
                *(uint4*)(st + ST_AL + r * ST_STRIDE + u * 16) = vreg[q + 2];
                *(uint4*)(st + ST_BH + r * ST_STRIDE + u * 16) = vreg[q + 4];
                *(uint4*)(st + ST_BL + r * ST_STRIDE + u * 16) = vreg[q + 6];
            }
        }
        __syncthreads();
    }

    // epilogue: bias + exact GELU + store
#pragma unroll
    for (int m = 0; m < 2; m++) {
        int o0 = wm * 32 + m * 16 + (lane >> 2);
        float bias0 = b_conv[o0];
        float bias1 = b_conv[o0 + 8];
#pragma unroll
        for (int n = 0; n < 8; n++) {
            int ng = n0 + wn * 64 + n * 8 + (lane & 3) * 2;
            float v0 = acc[m][n][0] + bias0;
            float v1 = acc[m][n][1] + bias0;
            float v2 = acc[m][n][2] + bias1;
            float v3 = acc[m][n][3] + bias1;
            v0 = 0.5f * v0 * (1.0f + erff(v0 * 0.70710678118654752f));
            v1 = 0.5f * v1 * (1.0f + erff(v1 * 0.70710678118654752f));
            v2 = 0.5f * v2 * (1.0f + erff(v2 * 0.70710678118654752f));
            v3 = 0.5f * v3 * (1.0f + erff(v3 * 0.70710678118654752f));
            *(float2*)(out + ((size_t)(b * 128 + o0)) * NN + ng)     = make_float2(v0, v1);
            *(float2*)(out + ((size_t)(b * 128 + o0 + 8)) * NN + ng) = make_float2(v2, v3);
        }
    }
}

// ---------------------------------------------------------------------------
extern "C" void kernel_launch(void* const* d_in, const int* in_sizes, int n_in,
                              void* d_out, int out_size) {
    const float* x      = (const float*)d_in[0];
    const float* w_spec = (const float*)d_in[1];
    const float* w_conv = (const float*)d_in[2];
    const float* b_conv = (const float*)d_in[3];
    float* out = (float*)d_out;

    cudaFuncSetAttribute(gemm_fwd_mma, cudaFuncAttributeMaxDynamicSharedMemorySize, SMEM_BYTES);
    cudaFuncSetAttribute(gemm_inv_mma, cudaFuncAttributeMaxDynamicSharedMemorySize, SMEM_BYTES);

    fill_Tf <<<(128 * NN) / 256, 256>>>();
    fill_Tt <<<(NN * 128) / 256, 256>>>();
    transpose_w<<<(MODES * CCH * 32) / 256, 256>>>(w_spec);
    prep_xt <<<dim3(NN / 32, 4, BB), dim3(32, 8)>>>(x);
    prep_wconv<<<(BB * 128 * 128) / 256, 256>>>(w_conv);

    gemm_fwd_mma<<<dim3(KSPLIT, 16), 256, SMEM_BYTES>>>(x);
    mode_mix<<<dim3(MODES, BB), 128>>>();
    gemm_inv_mma<<<dim3(NN / 128, BB), 256, SMEM_BYTES>>>(b_conv, out);
}

// round 5
// speedup vs baseline: 1.8464x; 1.2239x over previous
#include <cuda_runtime.h>
#include <cuda_bf16.h>
#include <math.h>
#include <stdint.h>

#define NN    8192
#define BB    16
#define CCH   128
#define MODES 64
#define KSPLIT 16

// ---------------- scratch (static device globals) ----------------
__device__ __nv_bfloat16 g_Tfh[128 * NN];                    // basis hi [j][n] (cos j<64, sin j>=64)
__device__ __nv_bfloat16 g_Tfl[128 * NN];                    // basis lo
__device__ float         g_Pt [(size_t)KSPLIT * BB * 128 * 128]; // fwd partials [ks][b][j][i]
__device__ float         g_Ft [BB * 128 * 128];              // reduced F [b][j][i]
__device__ float         g_wT [MODES * CCH * CCH * 2];       // [m][o][i][re,im]
__device__ __nv_bfloat16 g_Ch [BB * 128 * 128];              // coeffs hi [b][o][j]
__device__ __nv_bfloat16 g_Cl [BB * 128 * 128];              // coeffs lo
__device__ __nv_bfloat16 g_wch[128 * 128];                   // w_conv hi [o][i]
__device__ __nv_bfloat16 g_wcl[128 * 128];                   // w_conv lo

// ---------------- helpers ----------------
__device__ __forceinline__ uint32_t smem_u32(const void* p) {
    uint32_t a;
    asm("{ .reg .u64 t; cvta.to.shared.u64 t, %1; cvt.u32.u64 %0, t; }" : "=r"(a) : "l"(p));
    return a;
}
#define LDSM4(R, addr) \
    asm volatile("ldmatrix.sync.aligned.m8n8.x4.shared.b16 {%0,%1,%2,%3}, [%4];" \
        : "=r"((R)[0]), "=r"((R)[1]), "=r"((R)[2]), "=r"((R)[3]) : "r"(addr))
#define LDSM4T(R, addr) \
    asm volatile("ldmatrix.sync.aligned.m8n8.x4.trans.shared.b16 {%0,%1,%2,%3}, [%4];" \
        : "=r"((R)[0]), "=r"((R)[1]), "=r"((R)[2]), "=r"((R)[3]) : "r"(addr))
#define CP16(dst, src) \
    asm volatile("cp.async.cg.shared.global [%0], [%1], 16;" :: "r"(dst), "l"(src))
#define CPCOMMIT() asm volatile("cp.async.commit_group;" ::: "memory")
#define CPWAIT0()  asm volatile("cp.async.wait_group 0;" ::: "memory")

__device__ __forceinline__ void mma16816(float* c, const uint32_t* a, uint32_t b0, uint32_t b1) {
    asm volatile("mma.sync.aligned.m16n8k16.row.col.f32.bf16.bf16.f32 "
        "{%0,%1,%2,%3}, {%4,%5,%6,%7}, {%8,%9}, {%0,%1,%2,%3};"
        : "+f"(c[0]), "+f"(c[1]), "+f"(c[2]), "+f"(c[3])
        : "r"(a[0]), "r"(a[1]), "r"(a[2]), "r"(a[3]), "r"(b0), "r"(b1));
}
__device__ __forceinline__ uint32_t pack2(__nv_bfloat16 a, __nv_bfloat16 b) {
    return (uint32_t)__bfloat16_as_ushort(a) | ((uint32_t)__bfloat16_as_ushort(b) << 16);
}
__device__ __forceinline__ void split4(float4 v, uint2& hi, uint2& lo) {
    __nv_bfloat16 h0 = __float2bfloat16(v.x), h1 = __float2bfloat16(v.y);
    __nv_bfloat16 h2 = __float2bfloat16(v.z), h3 = __float2bfloat16(v.w);
    __nv_bfloat16 l0 = __float2bfloat16(v.x - __bfloat162float(h0));
    __nv_bfloat16 l1 = __float2bfloat16(v.y - __bfloat162float(h1));
    __nv_bfloat16 l2 = __float2bfloat16(v.z - __bfloat162float(h2));
    __nv_bfloat16 l3 = __float2bfloat16(v.w - __bfloat162float(h3));
    hi = make_uint2(pack2(h0, h1), pack2(h2, h3));
    lo = make_uint2(pack2(l0, l1), pack2(l2, l3));
}

// fwd stage layout: A [128 r][32 k] pitch 80; B [128 j][32 k] pitch 80
#define FAH 0
#define FAL 10240
#define FBH 20480
#define FBL 30720
#define FSZ 40960
#define FSMEM (2 * FSZ)
// inv stage layout: A [128 o][32 k] pitch 80; B [32 k][128 n] pitch 272
#define IAH 0
#define IAL 10240
#define IBH 20480
#define IBL 29184
#define ISZ 37888
#define ISMEM (2 * ISZ)

// ---------------------------------------------------------------------------
// Prep kernels
// ---------------------------------------------------------------------------
__global__ void fill_Tf() {
    int idx = blockIdx.x * blockDim.x + threadIdx.x;   // 128*8192, [j][n]
    int j = idx >> 13;
    int n = idx & (NN - 1);
    int m = j & 63;
    int t = (m * n) & (NN - 1);
    float s, c;
    sincospif((float)t * (1.0f / 4096.0f), &s, &c);
    float v = (j < MODES) ? c : s;
    __nv_bfloat16 h = __float2bfloat16(v);
    g_Tfh[idx] = h;
    g_Tfl[idx] = __float2bfloat16(v - __bfloat162float(h));
}

__global__ void transpose_w(const float* __restrict__ w_spec) {
    int idx = blockIdx.x * blockDim.x + threadIdx.x;   // 64*128*32
    int m  = idx & 63;
    int o  = (idx >> 6) & 127;
    int ib = idx >> 13;
    float2 v[4];
#pragma unroll
    for (int q = 0; q < 4; q++) {
        int i = ib * 4 + q;
        v[q] = *(const float2*)(w_spec + ((size_t)(i * CCH + o) * MODES + m) * 2);
    }
    float* dst = g_wT + ((size_t)(m * CCH + o) * CCH + ib * 4) * 2;
    *(float4*)(dst)     = make_float4(v[0].x, v[0].y, v[1].x, v[1].y);
    *(float4*)(dst + 4) = make_float4(v[2].x, v[2].y, v[3].x, v[3].y);
}

__global__ void prep_wc(const float* __restrict__ w_conv) {
    int idx = blockIdx.x * blockDim.x + threadIdx.x;   // 16384
    float v = w_conv[idx];
    __nv_bfloat16 h = __float2bfloat16(v);
    g_wch[idx] = h;
    g_wcl[idx] = __float2bfloat16(v - __bfloat162float(h));
}

// ---------------------------------------------------------------------------
// Compute: one 128x128x32 k-tile, fwd variant (B normal ldmatrix on [j][k])
// ---------------------------------------------------------------------------
__device__ __forceinline__ void compute_tile_f(float acc[2][8][4], uint32_t stg,
                                               int wm, int wn, int lane) {
#pragma unroll
    for (int s16 = 0; s16 < 2; s16++) {
        uint32_t ah[2][4], al[2][4];
        uint32_t aaddr = stg + FAH + (uint32_t)(wm * 32 + (lane & 15)) * 80
                       + s16 * 32 + (lane >> 4) * 16;
        LDSM4(ah[0], aaddr);
        LDSM4(ah[1], aaddr + 16 * 80);
        LDSM4(al[0], aaddr + (FAL - FAH));
        LDSM4(al[1], aaddr + (FAL - FAH) + 16 * 80);
        uint32_t n_off = (lane & 7) + ((lane >> 4) << 3);
        uint32_t kb = ((lane >> 3) & 1) * 16;
        uint32_t baddr = stg + FBH + (uint32_t)(wn * 64 + n_off) * 80 + s16 * 32 + kb;
#pragma unroll
        for (int nb = 0; nb < 4; nb++) {
            uint32_t bh[4], bl[4];
            LDSM4(bh, baddr + nb * 16 * 80);
            LDSM4(bl, baddr + nb * 16 * 80 + (FBL - FBH));
#pragma unroll
            for (int half = 0; half < 2; half++) {
                int n = nb * 2 + half;
#pragma unroll
                for (int m = 0; m < 2; m++) {
                    mma16816(acc[m][n], ah[m], bh[half * 2], bh[half * 2 + 1]);
                    mma16816(acc[m][n], ah[m], bl[half * 2], bl[half * 2 + 1]);
                    mma16816(acc[m][n], al[m], bh[half * 2], bh[half * 2 + 1]);
                }
            }
        }
    }
}

// inv variant: B via ldmatrix.trans on [k][n] layout (pitch 272)
__device__ __forceinline__ void compute_tile_i(float acc[2][8][4], uint32_t stg,
                                               int wm, int wn, int lane) {
#pragma unroll
    for (int s16 = 0; s16 < 2; s16++) {
        uint32_t ah[2][4], al[2][4];
        uint32_t aaddr = stg + IAH + (uint32_t)(wm * 32 + (lane & 15)) * 80
                       + s16 * 32 + (lane >> 4) * 16;
        LDSM4(ah[0], aaddr);
        LDSM4(ah[1], aaddr + 16 * 80);
        LDSM4(al[0], aaddr + (IAL - IAH));
        LDSM4(al[1], aaddr + (IAL - IAH) + 16 * 80);
        uint32_t baddr = stg + IBH + (uint32_t)(s16 * 16 + (lane & 15)) * 272
                       + (uint32_t)(wn * 64) * 2 + (lane >> 4) * 16;
#pragma unroll
        for (int nb = 0; nb < 4; nb++) {
            uint32_t bh[4], bl[4];
            LDSM4T(bh, baddr + nb * 32);
            LDSM4T(bl, baddr + nb * 32 + (IBL - IBH));
#pragma unroll
            for (int m = 0; m < 2; m++) {
                mma16816(acc[m][nb * 2], ah[m], bh[0], bh[1]);
                mma16816(acc[m][nb * 2], ah[m], bl[0], bl[1]);
                mma16816(acc[m][nb * 2], al[m], bh[0], bh[1]);
                mma16816(acc[m][nb * 2 + 1], ah[m], bh[2], bh[3]);
                mma16816(acc[m][nb * 2 + 1], ah[m], bl[2], bl[3]);
                mma16816(acc[m][nb * 2 + 1], al[m], bh[2], bh[3]);
            }
        }
    }
}

// ---------------------------------------------------------------------------
// Forward GEMM: Pt[ks][b][j][i] = sum_{k in chunk} x[b*128+i][k] * T[j][k]
// grid (KSPLIT, 16 b), 256 threads, 2 CTAs/SM
// ---------------------------------------------------------------------------
__global__ __launch_bounds__(256, 2) void gemm_fwd_mma(const float* __restrict__ x) {
    extern __shared__ char smem[];
    uint32_t sb = smem_u32(smem);
    int t = threadIdx.x, lane = t & 31, wid = t >> 5;
    int wm = wid & 3, wn = wid >> 2;
    int ks = blockIdx.x, b = blockIdx.y;
    int r0 = b * 128, kbase = ks * (NN / KSPLIT);
    const int NT = (NN / KSPLIT) / 32;   // 16

    float acc[2][8][4];
#pragma unroll
    for (int m = 0; m < 2; m++)
#pragma unroll
        for (int n = 0; n < 8; n++)
#pragma unroll
            for (int e = 0; e < 4; e++) acc[m][n][e] = 0.f;

    int arow = t >> 3, ak4 = t & 7;     // A: x, 4 chunks of (row += 32)
    int brow = t >> 2, bu = t & 3;      // B: T, 2 chunks of (row += 64)

    // prologue: stage 0
    {
        int k0 = kbase;
        uint32_t st = sb;
        float4 va[4];
#pragma unroll
        for (int q = 0; q < 4; q++)
            va[q] = *(const float4*)(x + (size_t)(r0 + arow + q * 32) * NN + k0 + ak4 * 4);
#pragma unroll
        for (int q = 0; q < 2; q++) {
            int row = brow + q * 64;
            CP16(st + FBH + row * 80 + bu * 16, g_Tfh + (size_t)row * NN + k0 + bu * 8);
            CP16(st + FBL + row * 80 + bu * 16, g_Tfl + (size_t)row * NN + k0 + bu * 8);
        }
        CPCOMMIT();
#pragma unroll
        for (int q = 0; q < 4; q++) {
            int row = arow + q * 32;
            uint2 hi, lo; split4(va[q], hi, lo);
            *(uint2*)(smem + FAH + row * 80 + ak4 * 8) = hi;
            *(uint2*)(smem + FAL + row * 80 + ak4 * 8) = lo;
        }
        CPWAIT0();
        __syncthreads();
    }

    for (int tile = 0; tile < NT; tile++) {
        int cur = tile & 1;
        bool hn = (tile + 1 < NT);
        float4 va[4];
        if (hn) {
            int k0 = kbase + (tile + 1) * 32;
            uint32_t stN = sb + (cur ^ 1) * FSZ;
#pragma unroll
            for (int q = 0; q < 4; q++)
                va[q] = *(const float4*)(x + (size_t)(r0 + arow + q * 32) * NN + k0 + ak4 * 4);
#pragma unroll
            for (int q = 0; q < 2; q++) {
                int row = brow + q * 64;
                CP16(stN + FBH + row * 80 + bu * 16, g_Tfh + (size_t)row * NN + k0 + bu * 8);
                CP16(stN + FBL + row * 80 + bu * 16, g_Tfl + (size_t)row * NN + k0 + bu * 8);
            }
            CPCOMMIT();
        }
        compute_tile_f(acc, sb + cur * FSZ, wm, wn, lane);
        if (hn) {
            char* stN = smem + (cur ^ 1) * FSZ;
#pragma unroll
            for (int q = 0; q < 4; q++) {
                int row = arow + q * 32;
                uint2 hi, lo; split4(va[q], hi, lo);
                *(uint2*)(stN + FAH + row * 80 + ak4 * 8) = hi;
                *(uint2*)(stN + FAL + row * 80 + ak4 * 8) = lo;
            }
            CPWAIT0();
        }
        __syncthreads();
    }

    // epilogue: transpose through SMEM -> g_Pt[ks][b][j][i]
    float* ftile = (float*)smem;   // [j][132] pitch
#pragma unroll
    for (int m = 0; m < 2; m++) {
        int r1 = wm * 32 + m * 16 + (lane >> 2);
#pragma unroll
        for (int n = 0; n < 8; n++) {
            int j = wn * 64 + n * 8 + (lane & 3) * 2;
            ftile[j * 132 + r1]           = acc[m][n][0];
            ftile[(j + 1) * 132 + r1]     = acc[m][n][1];
            ftile[j * 132 + r1 + 8]       = acc[m][n][2];
            ftile[(j + 1) * 132 + r1 + 8] = acc[m][n][3];
        }
    }
    __syncthreads();
    float* P = g_Pt + ((size_t)(ks * BB + b)) * 128 * 128;
#pragma unroll
    for (int w = 0; w < 16; w++) {
        int idx4 = t + w * 256;      // 4096 float4
        int j = idx4 >> 5, i4 = idx4 & 31;
        *(float4*)(P + (size_t)j * 128 + i4 * 4) = *(const float4*)&ftile[j * 132 + i4 * 4];
    }
}

// ---------------------------------------------------------------------------
// Reduce over ks: g_Ft = sum_ks g_Pt  (fully coalesced)
// ---------------------------------------------------------------------------
__global__ __launch_bounds__(256) void reduce_P() {
    int idx = blockIdx.x * 256 + threadIdx.x;   // 65536 float4
    const float4* P = (const float4*)g_Pt;
    float4 s = P[idx];
#pragma unroll
    for (int ks = 1; ks < KSPLIT; ks++) {
        float4 v = P[(size_t)ks * 65536 + idx];
        s.x += v.x; s.y += v.y; s.z += v.z; s.w += v.w;
    }
    ((float4*)g_Ft)[idx] = s;
}

// ---------------------------------------------------------------------------
// Mode mix -> bf16 hi/lo coefficients [b][o][j]
// grid (BB, MODES) with b fast so consecutive blocks share the w row in L2
// ---------------------------------------------------------------------------
__global__ __launch_bounds__(128) void mode_mix() {
    int b = blockIdx.x, m = blockIdx.y, o = threadIdx.x;
    __shared__ float Fre[128], Fim[128];
    Fre[o] =  g_Ft[((size_t)b * 128 + m) * 128 + o];
    Fim[o] = -g_Ft[((size_t)b * 128 + 64 + m) * 128 + o];
    __syncthreads();
    float aR = 0.f, aI = 0.f;
    const float2* wrow = (const float2*)g_wT + (size_t)(m * CCH + o) * CCH;
#pragma unroll 8
    for (int i = 0; i < CCH; i++) {
        float2 w = wrow[i];
        float fr = Fre[i], fi = Fim[i];
        aR = fmaf(fr, w.x, fmaf(-fi, w.y, aR));
        aI = fmaf(fr, w.y, fmaf( fi, w.x, aI));
    }
    float sR = (m == 0) ? (1.0f / (float)NN) : (2.0f / (float)NN);
    float sI = (m == 0) ? 0.0f : (-2.0f / (float)NN);
    float cR = aR * sR, cI = aI * sI;
    size_t base = ((size_t)b * 128 + o) * 128;
    __nv_bfloat16 hR = __float2bfloat16(cR);
    __nv_bfloat16 hI = __float2bfloat16(cI);
    g_Ch[base + m]      = hR;
    g_Cl[base + m]      = __float2bfloat16(cR - __bfloat162float(hR));
    g_Ch[base + 64 + m] = hI;
    g_Cl[base + 64 + m] = __float2bfloat16(cI - __bfloat162float(hI));
}

// ---------------------------------------------------------------------------
// Inverse GEMM (fused iDFT + conv1x1 + bias + exact GELU)
// D[o][n] = sum_k A[o][k]*B[k][n], K=256 (128 basis rows + 128 channels)
// B transposed on the fly via ldmatrix.trans. grid (64 n-tiles, 16 b)
// ---------------------------------------------------------------------------
__global__ __launch_bounds__(256, 2) void gemm_inv_mma(const float* __restrict__ x,
                                                       const float* __restrict__ b_conv,
                                                       float* __restrict__ out) {
    extern __shared__ char smem[];
    uint32_t sb = smem_u32(smem);
    int t = threadIdx.x, lane = t & 31, wid = t >> 5;
    int wm = wid & 3, wn = wid >> 2;
    int nt = blockIdx.x, b = blockIdx.y;
    int n0 = nt * 128;
    const int NT = 8;

    float acc[2][8][4];
#pragma unroll
    for (int m = 0; m < 2; m++)
#pragma unroll
        for (int n = 0; n < 8; n++)
#pragma unroll
            for (int e = 0; e < 4; e++) acc[m][n][e] = 0.f;

    const __nv_bfloat16* Chb = g_Ch + (size_t)b * 16384;
    const __nv_bfloat16* Clb = g_Cl + (size_t)b * 16384;

    // load one k-tile into stage st (A via cp.async; B: cp.async for T part,
    // register split for x part — x regs returned via vx, stored later)
#define INV_LOAD_ASYNC(K0, ST, VX, NX) do { \
    int _k0 = (K0); uint32_t _st = (ST); \
    const __nv_bfloat16 *_Ah, *_Al; int _kc; \
    if (_k0 < 128) { _Ah = Chb; _Al = Clb; _kc = _k0; } \
    else { _Ah = g_wch; _Al = g_wcl; _kc = _k0 - 128; } \
    { int _ar = t >> 1; \
      _Pragma("unroll") \
      for (int q = 0; q < 2; q++) { \
          int u = (t & 1) * 2 + q; \
          CP16(_st + IAH + _ar * 80 + u * 16, _Ah + _ar * 128 + _kc + u * 8); \
          CP16(_st + IAL + _ar * 80 + u * 16, _Al + _ar * 128 + _kc + u * 8); \
      } } \
    if (_k0 < 128) { \
        NX = false; \
        int _kr = t >> 3, _u = t & 7; \
        _Pragma("unroll") \
        for (int q = 0; q < 2; q++) { \
            int c8 = _u + q * 8; \
            CP16(_st + IBH + _kr * 272 + c8 * 16, g_Tfh + (size_t)(_k0 + _kr) * NN + n0 + c8 * 8); \
            CP16(_st + IBL + _kr * 272 + c8 * 16, g_Tfl + (size_t)(_k0 + _kr) * NN + n0 + c8 * 8); \
        } \
    } else { \
        NX = true; \
        int _kr = t >> 3; \
        _Pragma("unroll") \
        for (int q = 0; q < 4; q++) { \
            int c = (t & 7) + q * 8; \
            VX[q] = *(const float4*)(x + (size_t)(b * 128 + _k0 - 128 + _kr) * NN + n0 + c * 4); \
        } \
    } \
    CPCOMMIT(); \
} while (0)

#define INV_STORE_X(ST, VX) do { \
    char* _st = (ST); \
    int _kr = t >> 3; \
    _Pragma("unroll") \
    for (int q = 0; q < 4; q++) { \
        int c = (t & 7) + q * 8; \
        uint2 hi, lo; split4(VX[q], hi, lo); \
        *(uint2*)(_st + IBH + _kr * 272 + c * 8) = hi; \
        *(uint2*)(_st + IBL + _kr * 272 + c * 8) = lo; \
    } \
} while (0)

    // prologue
    {
        float4 vx[4]; bool nx;
        INV_LOAD_ASYNC(0, sb, vx, nx);
        if (nx) INV_STORE_X(smem, vx);   // (never taken for tile 0, kept for symmetry)
        CPWAIT0();
        __syncthreads();
    }

    for (int tile = 0; tile < NT; tile++) {
        int cur = tile & 1;
        bool hn = (tile + 1 < NT);
        float4 vx[4]; bool nx = false;
        if (hn) INV_LOAD_ASYNC((tile + 1) * 32, sb + (cur ^ 1) * ISZ, vx, nx);
        compute_tile_i(acc, sb + cur * ISZ, wm, wn, lane);
        if (hn) {
            if (nx) INV_STORE_X(smem + (cur ^ 1) * ISZ, vx);
            CPWAIT0();
        }
        __syncthreads();
    }

    // epilogue: bias + exact GELU + store
#pragma unroll
    for (int m = 0; m < 2; m++) {
        int o0 = wm * 32 + m * 16 + (lane >> 2);
        float bias0 = b_conv[o0];
        float bias1 = b_conv[o0 + 8];
#pragma unroll
        for (int n = 0; n < 8; n++) {
            int ng = n0 + wn * 64 + n * 8 + (lane & 3) * 2;
            float v0 = acc[m][n][0] + bias0;
            float v1 = acc[m][n][1] + bias0;
            float v2 = acc[m][n][2] + bias1;
            float v3 = acc[m][n][3] + bias1;
            v0 = 0.5f * v0 * (1.0f + erff(v0 * 0.70710678118654752f));
            v1 = 0.5f * v1 * (1.0f + erff(v1 * 0.70710678118654752f));
            v2 = 0.5f * v2 * (1.0f + erff(v2 * 0.70710678118654752f));
            v3 = 0.5f * v3 * (1.0f + erff(v3 * 0.70710678118654752f));
            *(float2*)(out + ((size_t)(b * 128 + o0)) * NN + ng)     = make_float2(v0, v1);
            *(float2*)(out + ((size_t)(b * 128 + o0 + 8)) * NN + ng) = make_float2(v2, v3);
        }
    }
}

// ---------------------------------------------------------------------------
extern "C" void kernel_launch(void* const* d_in, const int* in_sizes, int n_in,
                              void* d_out, int out_size) {
    const float* x      = (const float*)d_in[0];
    const float* w_spec = (const float*)d_in[1];
    const float* w_conv = (const float*)d_in[2];
    const float* b_conv = (const float*)d_in[3];
    float* out = (float*)d_out;

    cudaFuncSetAttribute(gemm_fwd_mma, cudaFuncAttributeMaxDynamicSharedMemorySize, FSMEM);
    cudaFuncSetAttribute(gemm_inv_mma, cudaFuncAttributeMaxDynamicSharedMemorySize, ISMEM);

    fill_Tf    <<<(128 * NN) / 256, 256>>>();
    transpose_w<<<(MODES * CCH * 32) / 256, 256>>>(w_spec);
    prep_wc    <<<(128 * 128) / 256, 256>>>(w_conv);

    gemm_fwd_mma<<<dim3(KSPLIT, BB), 256, FSMEM>>>(x);
    reduce_P    <<<256, 256>>>();
    mode_mix    <<<dim3(BB, MODES), 128>>>();
    gemm_inv_mma<<<dim3(NN / 128, BB), 256, ISMEM>>>(x, b_conv, out);
}

// round 6
// speedup vs baseline: 2.1735x; 1.1771x over previous
#include <cuda_runtime.h>
#include <cuda_fp16.h>
#include <math.h>
#include <stdint.h>

#define NN    8192
#define BB    16
#define CCH   128
#define MODES 64
#define KSPLIT 16

// ---------------- scratch ----------------
__device__ float  g_lutc[8192];                         // cos(2*pi*t/8192)
__device__ __half g_Th[128 * NN];                       // basis hi [j][n]
__device__ __half g_Tl[128 * NN];                       // basis lo
__device__ __half g_xh[(size_t)2048 * NN];              // x fp16 [r][n]
__device__ __half g_Ah[BB * 128 * 256];                 // inv A hi [b][o][k]
__device__ __half g_Al[BB * 128 * 256];                 // inv A lo
__device__ float  g_Pt[(size_t)KSPLIT * BB * 128 * 128];// fwd partials [ks][b][j][i]
__device__ float  g_Ft[BB * 128 * 128];                 // reduced [b][j][i]
__device__ float  g_wT[MODES * CCH * CCH * 2];          // [m][o][i][re,im]

// ---------------- helpers ----------------
__device__ __forceinline__ uint32_t smem_u32(const void* p) {
    uint32_t a;
    asm("{ .reg .u64 t; cvta.to.shared.u64 t, %1; cvt.u32.u64 %0, t; }" : "=r"(a) : "l"(p));
    return a;
}
#define LDSM4(R, addr) \
    asm volatile("ldmatrix.sync.aligned.m8n8.x4.shared.b16 {%0,%1,%2,%3}, [%4];" \
        : "=r"((R)[0]), "=r"((R)[1]), "=r"((R)[2]), "=r"((R)[3]) : "r"(addr))
#define LDSM4T(R, addr) \
    asm volatile("ldmatrix.sync.aligned.m8n8.x4.trans.shared.b16 {%0,%1,%2,%3}, [%4];" \
        : "=r"((R)[0]), "=r"((R)[1]), "=r"((R)[2]), "=r"((R)[3]) : "r"(addr))
#define CP16(dst, src) \
    asm volatile("cp.async.cg.shared.global [%0], [%1], 16;" :: "r"(dst), "l"(src))
#define CPCOMMIT() asm volatile("cp.async.commit_group;" ::: "memory")
#define CPWAIT0()  asm volatile("cp.async.wait_group 0;" ::: "memory")
#define CPWAIT1()  asm volatile("cp.async.wait_group 1;" ::: "memory")

__device__ __forceinline__ void mma16816(float* c, const uint32_t* a, uint32_t b0, uint32_t b1) {
    asm volatile("mma.sync.aligned.m16n8k16.row.col.f32.f16.f16.f32 "
        "{%0,%1,%2,%3}, {%4,%5,%6,%7}, {%8,%9}, {%0,%1,%2,%3};"
        : "+f"(c[0]), "+f"(c[1]), "+f"(c[2]), "+f"(c[3])
        : "r"(a[0]), "r"(a[1]), "r"(a[2]), "r"(a[3]), "r"(b0), "r"(b1));
}
__device__ __forceinline__ uint32_t packh(__half a, __half b) {
    return (uint32_t)__half_as_ushort(a) | ((uint32_t)__half_as_ushort(b) << 16);
}

// fwd stage: A hi [128 r][32 k] p80 ; B hi [128 j][32 k] p80 ; B lo same
#define FAH 0
#define FBH 10240
#define FBL 20480
#define FSZ 30720
#define FSMEM (3 * FSZ)
// inv stage: A hi [128 o][32 k] p80 ; A lo ; B [32 k][128 n] p272
#define IAH 0
#define IAL 10240
#define IB  20480
#define ISZ 29184
#define ISMEM (3 * ISZ)

// ---------------------------------------------------------------------------
// Prep
// ---------------------------------------------------------------------------
__global__ void lut_fill() {
    int t = blockIdx.x * 256 + threadIdx.x;   // 8192
    float s, c;
    sincospif((float)t * (1.0f / 4096.0f), &s, &c);
    g_lutc[t] = c;
}

__global__ void fill_T() {
    int idx = blockIdx.x * 256 + threadIdx.x;   // 128*8192
    int j = idx >> 13;
    int n = idx & (NN - 1);
    int m = j & 63;
    int t = (m * n) & (NN - 1);
    if (j >= MODES) t = (t + 6144) & (NN - 1);   // sin = cos shifted
    float v = g_lutc[t];
    __half h = __float2half(v);
    g_Th[idx] = h;
    g_Tl[idx] = __float2half(v - __half2float(h));
}

__global__ void transpose_w(const float* __restrict__ w_spec) {
    int idx = blockIdx.x * 256 + threadIdx.x;   // 64*128*32
    int m  = idx & 63;
    int o  = (idx >> 6) & 127;
    int ib = idx >> 13;
    float2 v[4];
#pragma unroll
    for (int q = 0; q < 4; q++) {
        int i = ib * 4 + q;
        v[q] = *(const float2*)(w_spec + ((size_t)(i * CCH + o) * MODES + m) * 2);
    }
    float* dst = g_wT + ((size_t)(m * CCH + o) * CCH + ib * 4) * 2;
    *(float4*)(dst)     = make_float4(v[0].x, v[0].y, v[1].x, v[1].y);
    *(float4*)(dst + 4) = make_float4(v[2].x, v[2].y, v[3].x, v[3].y);
}

__global__ void prep_split(const float* __restrict__ x) {
    int idx4 = blockIdx.x * 256 + threadIdx.x;     // 4.19M float4
    float4 v = ((const float4*)x)[idx4];
    ((uint2*)g_xh)[idx4] = make_uint2(
        packh(__float2half(v.x), __float2half(v.y)),
        packh(__float2half(v.z), __float2half(v.w)));
}

__global__ void prep_wc(const float* __restrict__ w_conv) {
    int idx = blockIdx.x * 256 + threadIdx.x;   // 16*128*128
    int b = idx >> 14;
    int o = (idx >> 7) & 127;
    int i = idx & 127;
    float v = w_conv[o * 128 + i];
    __half h = __float2half(v);
    size_t d = ((size_t)(b * 128 + o)) * 256 + 128 + i;
    g_Ah[d] = h;
    g_Al[d] = __float2half(v - __half2float(h));
}

// ---------------------------------------------------------------------------
// fwd compute: A hi single, B 2-pass (hi+lo). 64 MMA / warp / k32-tile.
// ---------------------------------------------------------------------------
__device__ __forceinline__ void compute_tile_f(float acc[2][8][4], uint32_t stg,
                                               int wm, int wn, int lane) {
#pragma unroll
    for (int s16 = 0; s16 < 2; s16++) {
        uint32_t ah[2][4];
        uint32_t aaddr = stg + FAH + (uint32_t)(wm * 32 + (lane & 15)) * 80
                       + s16 * 32 + (lane >> 4) * 16;
        LDSM4(ah[0], aaddr);
        LDSM4(ah[1], aaddr + 16 * 80);
        uint32_t n_off = (lane & 7) + ((lane >> 4) << 3);
        uint32_t kb = ((lane >> 3) & 1) * 16;
        uint32_t baddr = stg + FBH + (uint32_t)(wn * 64 + n_off) * 80 + s16 * 32 + kb;
#pragma unroll
        for (int nb = 0; nb < 4; nb++) {
            uint32_t bh[4], bl[4];
            LDSM4(bh, baddr + nb * 16 * 80);
            LDSM4(bl, baddr + nb * 16 * 80 + (FBL - FBH));
#pragma unroll
            for (int half = 0; half < 2; half++) {
                int n = nb * 2 + half;
#pragma unroll
                for (int m = 0; m < 2; m++) {
                    mma16816(acc[m][n], ah[m], bh[half * 2], bh[half * 2 + 1]);
                    mma16816(acc[m][n], ah[m], bl[half * 2], bl[half * 2 + 1]);
                }
            }
        }
    }
}

// inv compute: A 2-pass (hi+lo), B single via ldmatrix.trans
__device__ __forceinline__ void compute_tile_i(float acc[2][8][4], uint32_t stg,
                                               int wm, int wn, int lane) {
#pragma unroll
    for (int s16 = 0; s16 < 2; s16++) {
        uint32_t ah[2][4], al[2][4];
        uint32_t aaddr = stg + IAH + (uint32_t)(wm * 32 + (lane & 15)) * 80
                       + s16 * 32 + (lane >> 4) * 16;
        LDSM4(ah[0], aaddr);
        LDSM4(ah[1], aaddr + 16 * 80);
        LDSM4(al[0], aaddr + (IAL - IAH));
        LDSM4(al[1], aaddr + (IAL - IAH) + 16 * 80);
        uint32_t baddr = stg + IB + (uint32_t)(s16 * 16 + (lane & 15)) * 272
                       + (uint32_t)(wn * 64) * 2 + (lane >> 4) * 16;
#pragma unroll
        for (int nb = 0; nb < 4; nb++) {
            uint32_t bh[4];
            LDSM4T(bh, baddr + nb * 32);
#pragma unroll
            for (int m = 0; m < 2; m++) {
                mma16816(acc[m][nb * 2], ah[m], bh[0], bh[1]);
                mma16816(acc[m][nb * 2], al[m], bh[0], bh[1]);
                mma16816(acc[m][nb * 2 + 1], ah[m], bh[2], bh[3]);
                mma16816(acc[m][nb * 2 + 1], al[m], bh[2], bh[3]);
            }
        }
    }
}

// ---------------------------------------------------------------------------
// Forward GEMM: Pt[ks][b][j][i] = sum_k xh[b*128+i][k] * T[j][k]
// grid (BB, KSPLIT) — b fast so CTAs sharing a T chunk are adjacent
// ---------------------------------------------------------------------------
__global__ __launch_bounds__(256, 2) void gemm_fwd_mma() {
    extern __shared__ char smem[];
    uint32_t sb = smem_u32(smem);
    int t = threadIdx.x, lane = t & 31, wid = t >> 5;
    int wm = wid & 3, wn = wid >> 2;
    int b = blockIdx.x, ks = blockIdx.y;
    int r0 = b * 128, kbase = ks * (NN / KSPLIT);
    const int NT = (NN / KSPLIT) / 32;   // 16

    float acc[2][8][4];
#pragma unroll
    for (int m = 0; m < 2; m++)
#pragma unroll
        for (int n = 0; n < 8; n++)
#pragma unroll
            for (int e = 0; e < 4; e++) acc[m][n][e] = 0.f;

#define FWD_ISSUE(T) do { \
    int _k0 = kbase + (T) * 32; \
    uint32_t _st = sb + ((T) % 3) * FSZ; \
    _Pragma("unroll") \
    for (int q = 0; q < 2; q++) { \
        int c = t + q * 256, row = c >> 2, u = c & 3; \
        CP16(_st + FAH + row * 80 + u * 16, g_xh + (size_t)(r0 + row) * NN + _k0 + u * 8); \
        CP16(_st + FBH + row * 80 + u * 16, g_Th + (size_t)row * NN + _k0 + u * 8); \
        CP16(_st + FBL + row * 80 + u * 16, g_Tl + (size_t)row * NN + _k0 + u * 8); \
    } \
    CPCOMMIT(); \
} while (0)

    FWD_ISSUE(0);
    FWD_ISSUE(1);
#pragma unroll 4
    for (int tile = 0; tile < NT; tile++) {
        if (tile + 1 < NT) { CPWAIT1(); } else { CPWAIT0(); }
        __syncthreads();
        compute_tile_f(acc, sb + (tile % 3) * FSZ, wm, wn, lane);
        if (tile + 2 < NT) FWD_ISSUE(tile + 2);
    }
    __syncthreads();

    // epilogue: transpose through SMEM -> g_Pt[ks][b][j][i]
    float* ftile = (float*)smem;   // [j][132]
#pragma unroll
    for (int m = 0; m < 2; m++) {
        int r1 = wm * 32 + m * 16 + (lane >> 2);
#pragma unroll
        for (int n = 0; n < 8; n++) {
            int j = wn * 64 + n * 8 + (lane & 3) * 2;
            ftile[j * 132 + r1]           = acc[m][n][0];
            ftile[(j + 1) * 132 + r1]     = acc[m][n][1];
            ftile[j * 132 + r1 + 8]       = acc[m][n][2];
            ftile[(j + 1) * 132 + r1 + 8] = acc[m][n][3];
        }
    }
    __syncthreads();
    float* P = g_Pt + ((size_t)(ks * BB + b)) * 128 * 128;
#pragma unroll
    for (int w = 0; w < 16; w++) {
        int idx4 = t + w * 256;
        int j = idx4 >> 5, i4 = idx4 & 31;
        *(float4*)(P + (size_t)j * 128 + i4 * 4) = *(const float4*)&ftile[j * 132 + i4 * 4];
    }
}

// ---------------------------------------------------------------------------
__global__ __launch_bounds__(256) void reduce_P() {
    int idx = blockIdx.x * 256 + threadIdx.x;
    const float4* P = (const float4*)g_Pt;
    float4 s = P[idx];
#pragma unroll
    for (int ks = 1; ks < KSPLIT; ks++) {
        float4 v = P[(size_t)ks * 65536 + idx];
        s.x += v.x; s.y += v.y; s.z += v.z; s.w += v.w;
    }
    ((float4*)g_Ft)[idx] = s;
}

// ---------------------------------------------------------------------------
// Mode mix -> fp16 hi/lo coefficients into g_Ah/g_Al [b][o][k<128]
// ---------------------------------------------------------------------------
__global__ __launch_bounds__(128) void mode_mix() {
    int b = blockIdx.x, m = blockIdx.y, o = threadIdx.x;
    __shared__ float Fre[128], Fim[128];
    Fre[o] =  g_Ft[((size_t)b * 128 + m) * 128 + o];
    Fim[o] = -g_Ft[((size_t)b * 128 + 64 + m) * 128 + o];
    __syncthreads();
    float aR = 0.f, aI = 0.f;
    const float2* wrow = (const float2*)g_wT + (size_t)(m * CCH + o) * CCH;
#pragma unroll 8
    for (int i = 0; i < CCH; i++) {
        float2 w = wrow[i];
        float fr = Fre[i], fi = Fim[i];
        aR = fmaf(fr, w.x, fmaf(-fi, w.y, aR));
        aI = fmaf(fr, w.y, fmaf( fi, w.x, aI));
    }
    float sR = (m == 0) ? (1.0f / (float)NN) : (2.0f / (float)NN);
    float sI = (m == 0) ? 0.0f : (-2.0f / (float)NN);
    float cR = aR * sR, cI = aI * sI;
    size_t base = ((size_t)(b * 128 + o)) * 256;
    __half hR = __float2half(cR);
    __half hI = __float2half(cI);
    g_Ah[base + m]      = hR;
    g_Al[base + m]      = __float2half(cR - __half2float(hR));
    g_Ah[base + 64 + m] = hI;
    g_Al[base + 64 + m] = __float2half(cI - __half2float(hI));
}

// ---------------------------------------------------------------------------
// Inverse GEMM (fused iDFT + conv1x1 + bias + exact GELU)
// D[o][n] = sum_k A[o][k]*B[k][n], K=256. grid (64 n-tiles, 16 b)
// ---------------------------------------------------------------------------
__global__ __launch_bounds__(256, 2) void gemm_inv_mma(const float* __restrict__ b_conv,
                                                       float* __restrict__ out) {
    extern __shared__ char smem[];
    uint32_t sb = smem_u32(smem);
    int t = threadIdx.x, lane = t & 31, wid = t >> 5;
    int wm = wid & 3, wn = wid >> 2;
    int nt = blockIdx.x, b = blockIdx.y;
    int n0 = nt * 128;
    const int NT = 8;

    const __half* Ahb = g_Ah + (size_t)b * 32768;
    const __half* Alb = g_Al + (size_t)b * 32768;

    float acc[2][8][4];
#pragma unroll
    for (int m = 0; m < 2; m++)
#pragma unroll
        for (int n = 0; n < 8; n++)
#pragma unroll
            for (int e = 0; e < 4; e++) acc[m][n][e] = 0.f;

#define INV_ISSUE(T) do { \
    int _k0 = (T) * 32; \
    uint32_t _st = sb + ((T) % 3) * ISZ; \
    _Pragma("unroll") \
    for (int q = 0; q < 2; q++) { \
        int c = t + q * 256, row = c >> 2, u = c & 3; \
        CP16(_st + IAH + row * 80 + u * 16, Ahb + (size_t)row * 256 + _k0 + u * 8); \
        CP16(_st + IAL + row * 80 + u * 16, Alb + (size_t)row * 256 + _k0 + u * 8); \
    } \
    _Pragma("unroll") \
    for (int q = 0; q < 2; q++) { \
        int c = t + q * 256, kr = c >> 4, cc = c & 15; \
        int _k = _k0 + kr; \
        const __half* src = (_k < 128) ? (g_Th + (size_t)_k * NN + n0) \
                                       : (g_xh + (size_t)(b * 128 + _k - 128) * NN + n0); \
        CP16(_st + IB + kr * 272 + cc * 16, src + cc * 8); \
    } \
    CPCOMMIT(); \
} while (0)

    INV_ISSUE(0);
    INV_ISSUE(1);
#pragma unroll
    for (int tile = 0; tile < NT; tile++) {
        if (tile + 1 < NT) { CPWAIT1(); } else { CPWAIT0(); }
        __syncthreads();
        compute_tile_i(acc, sb + (tile % 3) * ISZ, wm, wn, lane);
        if (tile + 2 < NT) INV_ISSUE(tile + 2);
    }

    // epilogue: bias + exact GELU + store
#pragma unroll
    for (int m = 0; m < 2; m++) {
        int o0 = wm * 32 + m * 16 + (lane >> 2);
        float bias0 = b_conv[o0];
        float bias1 = b_conv[o0 + 8];
#pragma unroll
        for (int n = 0; n < 8; n++) {
            int ng = n0 + wn * 64 + n * 8 + (lane & 3) * 2;
            float v0 = acc[m][n][0] + bias0;
            float v1 = acc[m][n][1] + bias0;
            float v2 = acc[m][n][2] + bias1;
            float v3 = acc[m][n][3] + bias1;
            v0 = 0.5f * v0 * (1.0f + erff(v0 * 0.70710678118654752f));
            v1 = 0.5f * v1 * (1.0f + erff(v1 * 0.70710678118654752f));
            v2 = 0.5f * v2 * (1.0f + erff(v2 * 0.70710678118654752f));
            v3 = 0.5f * v3 * (1.0f + erff(v3 * 0.70710678118654752f));
            *(float2*)(out + ((size_t)(b * 128 + o0)) * NN + ng)     = make_float2(v0, v1);
            *(float2*)(out + ((size_t)(b * 128 + o0 + 8)) * NN + ng) = make_float2(v2, v3);
        }
    }
}

// ---------------------------------------------------------------------------
extern "C" void kernel_launch(void* const* d_in, const int* in_sizes, int n_in,
                              void* d_out, int out_size) {
    const float* x      = (const float*)d_in[0];
    const float* w_spec = (const float*)d_in[1];
    const float* w_conv = (const float*)d_in[2];
    const float* b_conv = (const float*)d_in[3];
    float* out = (float*)d_out;

    cudaFuncSetAttribute(gemm_fwd_mma, cudaFuncAttributeMaxDynamicSharedMemorySize, FSMEM);
    cudaFuncSetAttribute(gemm_inv_mma, cudaFuncAttributeMaxDynamicSharedMemorySize, ISMEM);

    lut_fill   <<<32, 256>>>();
    fill_T     <<<(128 * NN) / 256, 256>>>();
    transpose_w<<<(MODES * CCH * 32) / 256, 256>>>(w_spec);
    prep_split <<<(2048 * NN / 4) / 256, 256>>>(x);
    prep_wc    <<<(BB * 128 * 128) / 256, 256>>>(w_conv);

    gemm_fwd_mma<<<dim3(BB, KSPLIT), 256, FSMEM>>>();
    reduce_P    <<<256, 256>>>();
    mode_mix    <<<dim3(BB, MODES), 128>>>();
    gemm_inv_mma<<<dim3(NN / 128, BB), 256, ISMEM>>>(b_conv, out);
}

// round 7
// speedup vs baseline: 3.0538x; 1.4050x over previous
#include <cuda_runtime.h>
#include <cuda_fp16.h>
#include <math.h>
#include <stdint.h>

#define NN    8192
#define BB    16
#define CCH   128
#define MODES 64
#define KSPLIT 16

// ---------------- scratch ----------------
__device__ float  g_lutc[8192];                          // cos(2*pi*t/8192)
__device__ __half g_Th[128 * NN];                        // basis fp16 [j][n]
__device__ __half g_xh[(size_t)2048 * NN];               // x fp16 [r][n]
__device__ __half g_Ah[BB * 128 * 256];                  // inv A fp16 [b][o][k]
__device__ float  g_Pt[(size_t)KSPLIT * BB * 128 * 128]; // fwd partials [ks][b][j][i]
__device__ float  g_Ft[BB * 128 * 128];                  // reduced [b][j][i]
__device__ float  g_wT[MODES * CCH * CCH * 2];           // [m][o][i][re,im]

// ---------------- helpers ----------------
__device__ __forceinline__ uint32_t smem_u32(const void* p) {
    uint32_t a;
    asm("{ .reg .u64 t; cvta.to.shared.u64 t, %1; cvt.u32.u64 %0, t; }" : "=r"(a) : "l"(p));
    return a;
}
#define LDSM4(R, addr) \
    asm volatile("ldmatrix.sync.aligned.m8n8.x4.shared.b16 {%0,%1,%2,%3}, [%4];" \
        : "=r"((R)[0]), "=r"((R)[1]), "=r"((R)[2]), "=r"((R)[3]) : "r"(addr))
#define LDSM4T(R, addr) \
    asm volatile("ldmatrix.sync.aligned.m8n8.x4.trans.shared.b16 {%0,%1,%2,%3}, [%4];" \
        : "=r"((R)[0]), "=r"((R)[1]), "=r"((R)[2]), "=r"((R)[3]) : "r"(addr))
#define CP16(dst, src) \
    asm volatile("cp.async.cg.shared.global [%0], [%1], 16;" :: "r"(dst), "l"(src))
#define CPCOMMIT() asm volatile("cp.async.commit_group;" ::: "memory")
#define CPWAIT0()  asm volatile("cp.async.wait_group 0;" ::: "memory")
#define CPWAIT1()  asm volatile("cp.async.wait_group 1;" ::: "memory")

__device__ __forceinline__ void mma16816(float* c, const uint32_t* a, uint32_t b0, uint32_t b1) {
    asm volatile("mma.sync.aligned.m16n8k16.row.col.f32.f16.f16.f32 "
        "{%0,%1,%2,%3}, {%4,%5,%6,%7}, {%8,%9}, {%0,%1,%2,%3};"
        : "+f"(c[0]), "+f"(c[1]), "+f"(c[2]), "+f"(c[3])
        : "r"(a[0]), "r"(a[1]), "r"(a[2]), "r"(a[3]), "r"(b0), "r"(b1));
}
__device__ __forceinline__ uint32_t packh(__half a, __half b) {
    return (uint32_t)__half_as_ushort(a) | ((uint32_t)__half_as_ushort(b) << 16);
}

// stage layouts (k-tile = 64, pitch 144 = 128+16)
// fwd: A [128 r][64 k] @0 ; B [128 j][64 k] @18432
#define FB_OFF 18432
#define FSZ    36864
#define FSMEM  (3 * FSZ)
// inv: A [128 o][64 k] @0 p144 ; B [64 k][128 n] @18432 p272
#define IB_OFF 18432
#define ISZ    36864
#define ISMEM  (3 * ISZ)

// ---------------------------------------------------------------------------
// Prep
// ---------------------------------------------------------------------------
__global__ void lut_fill() {
    int t = blockIdx.x * 256 + threadIdx.x;   // 8192
    float s, c;
    sincospif((float)t * (1.0f / 4096.0f), &s, &c);
    g_lutc[t] = c;
}

__global__ void fill_T() {
    int idx = blockIdx.x * 256 + threadIdx.x;   // 128*8192
    int j = idx >> 13;
    int n = idx & (NN - 1);
    int m = j & 63;
    int t = (m * n) & (NN - 1);
    if (j >= MODES) t = (t + 6144) & (NN - 1);   // sin = cos shifted
    g_Th[idx] = __float2half(g_lutc[t]);
}

__global__ void transpose_w(const float* __restrict__ w_spec) {
    int idx = blockIdx.x * 256 + threadIdx.x;   // 64*128*32
    int m  = idx & 63;
    int o  = (idx >> 6) & 127;
    int ib = idx >> 13;
    float2 v[4];
#pragma unroll
    for (int q = 0; q < 4; q++) {
        int i = ib * 4 + q;
        v[q] = *(const float2*)(w_spec + ((size_t)(i * CCH + o) * MODES + m) * 2);
    }
    float* dst = g_wT + ((size_t)(m * CCH + o) * CCH + ib * 4) * 2;
    *(float4*)(dst)     = make_float4(v[0].x, v[0].y, v[1].x, v[1].y);
    *(float4*)(dst + 4) = make_float4(v[2].x, v[2].y, v[3].x, v[3].y);
}

__global__ void prep_split(const float* __restrict__ x) {
    int idx4 = blockIdx.x * 256 + threadIdx.x;     // 4.19M float4
    float4 v = ((const float4*)x)[idx4];
    ((uint2*)g_xh)[idx4] = make_uint2(
        packh(__float2half(v.x), __float2half(v.y)),
        packh(__float2half(v.z), __float2half(v.w)));
}

__global__ void prep_wc(const float* __restrict__ w_conv) {
    int idx = blockIdx.x * 256 + threadIdx.x;   // 16*128*128
    int b = idx >> 14;
    int o = (idx >> 7) & 127;
    int i = idx & 127;
    g_Ah[((size_t)(b * 128 + o)) * 256 + 128 + i] = __float2half(w_conv[o * 128 + i]);
}

// ---------------------------------------------------------------------------
// fwd compute: one 128x128x64 tile, single-pass fp16
// ---------------------------------------------------------------------------
__device__ __forceinline__ void compute_tile_f(float acc[2][8][4], uint32_t stg,
                                               int wm, int wn, int lane) {
    uint32_t n_off = (lane & 7) + ((lane >> 4) << 3);
    uint32_t kb = ((lane >> 3) & 1) * 16;
#pragma unroll
    for (int s16 = 0; s16 < 4; s16++) {
        uint32_t ah[2][4];
        uint32_t aaddr = stg + (uint32_t)(wm * 32 + (lane & 15)) * 144
                       + s16 * 32 + (lane >> 4) * 16;
        LDSM4(ah[0], aaddr);
        LDSM4(ah[1], aaddr + 16 * 144);
        uint32_t baddr = stg + FB_OFF + (uint32_t)(wn * 64 + n_off) * 144 + s16 * 32 + kb;
#pragma unroll
        for (int nb = 0; nb < 4; nb++) {
            uint32_t bh[4];
            LDSM4(bh, baddr + nb * 16 * 144);
#pragma unroll
            for (int half = 0; half < 2; half++) {
                int n = nb * 2 + half;
#pragma unroll
                for (int m = 0; m < 2; m++)
                    mma16816(acc[m][n], ah[m], bh[half * 2], bh[half * 2 + 1]);
            }
        }
    }
}

// inv compute: B via ldmatrix.trans on [k][n] layout (pitch 272)
__device__ __forceinline__ void compute_tile_i(float acc[2][8][4], uint32_t stg,
                                               int wm, int wn, int lane) {
#pragma unroll
    for (int s16 = 0; s16 < 4; s16++) {
        uint32_t ah[2][4];
        uint32_t aaddr = stg + (uint32_t)(wm * 32 + (lane & 15)) * 144
                       + s16 * 32 + (lane >> 4) * 16;
        LDSM4(ah[0], aaddr);
        LDSM4(ah[1], aaddr + 16 * 144);
        uint32_t baddr = stg + IB_OFF + (uint32_t)(s16 * 16 + (lane & 15)) * 272
                       + (uint32_t)(wn * 64) * 2 + (lane >> 4) * 16;
#pragma unroll
        for (int nb = 0; nb < 4; nb++) {
            uint32_t bh[4];
            LDSM4T(bh, baddr + nb * 32);
#pragma unroll
            for (int m = 0; m < 2; m++) {
                mma16816(acc[m][nb * 2],     ah[m], bh[0], bh[1]);
                mma16816(acc[m][nb * 2 + 1], ah[m], bh[2], bh[3]);
            }
        }
    }
}

// ---------------------------------------------------------------------------
// Forward GEMM: Pt[ks][b][j][i] = sum_k xh[b*128+i][k] * T[j][k]
// grid (BB, KSPLIT), 256 threads, 2 CTAs/SM; K-chunk 512 = 8 k64-tiles
// ---------------------------------------------------------------------------
__global__ __launch_bounds__(256, 2) void gemm_fwd_mma() {
    extern __shared__ char smem[];
    uint32_t sb = smem_u32(smem);
    int t = threadIdx.x, lane = t & 31, wid = t >> 5;
    int wm = wid & 3, wn = wid >> 2;
    int b = blockIdx.x, ks = blockIdx.y;
    int r0 = b * 128, kbase = ks * (NN / KSPLIT);
    const int NT = (NN / KSPLIT) / 64;   // 8

    float acc[2][8][4];
#pragma unroll
    for (int m = 0; m < 2; m++)
#pragma unroll
        for (int n = 0; n < 8; n++)
#pragma unroll
            for (int e = 0; e < 4; e++) acc[m][n][e] = 0.f;

#define FWD_ISSUE(T) do { \
    int _k0 = kbase + (T) * 64; \
    uint32_t _st = sb + ((T) % 3) * FSZ; \
    _Pragma("unroll") \
    for (int q = 0; q < 4; q++) { \
        int c = t + q * 256, row = c >> 3, u = c & 7; \
        CP16(_st + row * 144 + u * 16, g_xh + (size_t)(r0 + row) * NN + _k0 + u * 8); \
        CP16(_st + FB_OFF + row * 144 + u * 16, g_Th + (size_t)row * NN + _k0 + u * 8); \
    } \
    CPCOMMIT(); \
} while (0)

    FWD_ISSUE(0);
    FWD_ISSUE(1);
#pragma unroll
    for (int tile = 0; tile < NT; tile++) {
        if (tile + 1 < NT) { CPWAIT1(); } else { CPWAIT0(); }
        __syncthreads();
        compute_tile_f(acc, sb + (tile % 3) * FSZ, wm, wn, lane);
        if (tile + 2 < NT) FWD_ISSUE(tile + 2);
    }
    __syncthreads();

    // epilogue: transpose through SMEM -> g_Pt[ks][b][j][i]
    float* ftile = (float*)smem;   // [j][132]
#pragma unroll
    for (int m = 0; m < 2; m++) {
        int r1 = wm * 32 + m * 16 + (lane >> 2);
#pragma unroll
        for (int n = 0; n < 8; n++) {
            int j = wn * 64 + n * 8 + (lane & 3) * 2;
            ftile[j * 132 + r1]           = acc[m][n][0];
            ftile[(j + 1) * 132 + r1]     = acc[m][n][1];
            ftile[j * 132 + r1 + 8]       = acc[m][n][2];
            ftile[(j + 1) * 132 + r1 + 8] = acc[m][n][3];
        }
    }
    __syncthreads();
    float* P = g_Pt + ((size_t)(ks * BB + b)) * 128 * 128;
#pragma unroll
    for (int w = 0; w < 16; w++) {
        int idx4 = t + w * 256;
        int j = idx4 >> 5, i4 = idx4 & 31;
        *(float4*)(P + (size_t)j * 128 + i4 * 4) = *(const float4*)&ftile[j * 132 + i4 * 4];
    }
}

// ---------------------------------------------------------------------------
__global__ __launch_bounds__(256) void reduce_P() {
    int idx = blockIdx.x * 256 + threadIdx.x;
    const float4* P = (const float4*)g_Pt;
    float4 s = P[idx];
#pragma unroll
    for (int ks = 1; ks < KSPLIT; ks++) {
        float4 v = P[(size_t)ks * 65536 + idx];
        s.x += v.x; s.y += v.y; s.z += v.z; s.w += v.w;
    }
    ((float4*)g_Ft)[idx] = s;
}

// ---------------------------------------------------------------------------
// Mode mix -> fp16 coefficients into g_Ah [b][o][k<128]
// grid (64 m, 4 bg): each block does 4 batches per w-row read
// ---------------------------------------------------------------------------
__global__ __launch_bounds__(256) void mode_mix() {
    int m = blockIdx.x, bg = blockIdx.y;
    int t = threadIdx.x;
    __shared__ float Fre[4][128], Fim[4][128];
#pragma unroll
    for (int q = 0; q < 2; q++) {
        int flat = t + q * 256;
        int bq = flat >> 7, i = flat & 127;
        int b = bg * 4 + bq;
        Fre[bq][i] =  g_Ft[((size_t)(b * 128) + m) * 128 + i];
        Fim[bq][i] = -g_Ft[((size_t)(b * 128) + 64 + m) * 128 + i];
    }
    __syncthreads();
    int o = t & 127, half = t >> 7;   // half handles batches half*2, half*2+1
    float aR[2] = {0.f, 0.f}, aI[2] = {0.f, 0.f};
    const float2* wrow = (const float2*)g_wT + (size_t)(m * CCH + o) * CCH;
#pragma unroll 8
    for (int i = 0; i < CCH; i++) {
        float2 w = wrow[i];
#pragma unroll
        for (int p = 0; p < 2; p++) {
            int bq = half * 2 + p;
            float fr = Fre[bq][i], fi = Fim[bq][i];
            aR[p] = fmaf(fr, w.x, fmaf(-fi, w.y, aR[p]));
            aI[p] = fmaf(fr, w.y, fmaf( fi, w.x, aI[p]));
        }
    }
    float sR = (m == 0) ? (1.0f / (float)NN) : (2.0f / (float)NN);
    float sI = (m == 0) ? 0.0f : (-2.0f / (float)NN);
#pragma unroll
    for (int p = 0; p < 2; p++) {
        int b = bg * 4 + half * 2 + p;
        size_t base = ((size_t)(b * 128 + o)) * 256;
        g_Ah[base + m]      = __float2half(aR[p] * sR);
        g_Ah[base + 64 + m] = __float2half(aI[p] * sI);
    }
}

// ---------------------------------------------------------------------------
// Inverse GEMM (fused iDFT + conv1x1 + bias + exact GELU)
// D[o][n] = sum_k A[o][k]*B[k][n], K=256 = 4 k64-tiles. grid (64 nt, 16 b)
// ---------------------------------------------------------------------------
__global__ __launch_bounds__(256, 2) void gemm_inv_mma(const float* __restrict__ b_conv,
                                                       float* __restrict__ out) {
    extern __shared__ char smem[];
    uint32_t sb = smem_u32(smem);
    int t = threadIdx.x, lane = t & 31, wid = t >> 5;
    int wm = wid & 3, wn = wid >> 2;
    int nt = blockIdx.x, b = blockIdx.y;
    int n0 = nt * 128;
    const int NT = 4;

    const __half* Ahb = g_Ah + (size_t)b * 32768;

    float acc[2][8][4];
#pragma unroll
    for (int m = 0; m < 2; m++)
#pragma unroll
        for (int n = 0; n < 8; n++)
#pragma unroll
            for (int e = 0; e < 4; e++) acc[m][n][e] = 0.f;

#define INV_ISSUE(T) do { \
    int _k0 = (T) * 64; \
    uint32_t _st = sb + ((T) % 3) * ISZ; \
    _Pragma("unroll") \
    for (int q = 0; q < 4; q++) { \
        int c = t + q * 256, row = c >> 3, u = c & 7; \
        CP16(_st + row * 144 + u * 16, Ahb + (size_t)row * 256 + _k0 + u * 8); \
    } \
    _Pragma("unroll") \
    for (int q = 0; q < 4; q++) { \
        int c = t + q * 256, kr = c >> 4, cc = c & 15; \
        int _k = _k0 + kr; \
        const __half* src = (_k < 128) ? (g_Th + (size_t)_k * NN + n0) \
                                       : (g_xh + (size_t)(b * 128 + _k - 128) * NN + n0); \
        CP16(_st + IB_OFF + kr * 272 + cc * 16, src + cc * 8); \
    } \
    CPCOMMIT(); \
} while (0)

    INV_ISSUE(0);
    INV_ISSUE(1);
#pragma unroll
    for (int tile = 0; tile < NT; tile++) {
        if (tile + 1 < NT) { CPWAIT1(); } else { CPWAIT0(); }
        __syncthreads();
        compute_tile_i(acc, sb + (tile % 3) * ISZ, wm, wn, lane);
        if (tile + 2 < NT) INV_ISSUE(tile + 2);
    }

    // epilogue: bias + exact GELU + store
#pragma unroll
    for (int m = 0; m < 2; m++) {
        int o0 = wm * 32 + m * 16 + (lane >> 2);
        float bias0 = b_conv[o0];
        float bias1 = b_conv[o0 + 8];
#pragma unroll
        for (int n = 0; n < 8; n++) {
            int ng = n0 + wn * 64 + n * 8 + (lane & 3) * 2;
            float v0 = acc[m][n][0] + bias0;
            float v1 = acc[m][n][1] + bias0;
            float v2 = acc[m][n][2] + bias1;
            float v3 = acc[m][n][3] + bias1;
            v0 = 0.5f * v0 * (1.0f + erff(v0 * 0.70710678118654752f));
            v1 = 0.5f * v1 * (1.0f + erff(v1 * 0.70710678118654752f));
            v2 = 0.5f * v2 * (1.0f + erff(v2 * 0.70710678118654752f));
            v3 = 0.5f * v3 * (1.0f + erff(v3 * 0.70710678118654752f));
            *(float2*)(out + ((size_t)(b * 128 + o0)) * NN + ng)     = make_float2(v0, v1);
            *(float2*)(out + ((size_t)(b * 128 + o0 + 8)) * NN + ng) = make_float2(v2, v3);
        }
    }
}

// ---------------------------------------------------------------------------
extern "C" void kernel_launch(void* const* d_in, const int* in_sizes, int n_in,
                              void* d_out, int out_size) {
    const float* x      = (const float*)d_in[0];
    const float* w_spec = (const float*)d_in[1];
    const float* w_conv = (const float*)d_in[2];
    const float* b_conv = (const float*)d_in[3];
    float* out = (float*)d_out;

    cudaFuncSetAttribute(gemm_fwd_mma, cudaFuncAttributeMaxDynamicSharedMemorySize, FSMEM);
    cudaFuncSetAttribute(gemm_inv_mma, cudaFuncAttributeMaxDynamicSharedMemorySize, ISMEM);

    lut_fill   <<<32, 256>>>();
    fill_T     <<<(128 * NN) / 256, 256>>>();
    transpose_w<<<(MODES * CCH * 32) / 256, 256>>>(w_spec);
    prep_split <<<(2048 * NN / 4) / 256, 256>>>(x);
    prep_wc    <<<(BB * 128 * 128) / 256, 256>>>(w_conv);

    gemm_fwd_mma<<<dim3(BB, KSPLIT), 256, FSMEM>>>();
    reduce_P    <<<256, 256>>>();
    mode_mix    <<<dim3(MODES, 4), 256>>>();
    gemm_inv_mma<<<dim3(NN / 128, BB), 256, ISMEM>>>(b_conv, out);
}